// round 10
// baseline (speedup 1.0000x reference)
#include <cuda_runtime.h>
#include <math.h>

#define T_DIM 1024
#define EPS 1e-7f
#define MARGIN 0.1f
#define MONO_W 0.1f
#define BETA 0.1f

#define BDIM 256            // 256 threads * float4 = 1024 cols = one row
#define ROWS 8              // rows per block
#define MAXB 32768
#define MAXBLK (MAXB / ROWS)

// Deterministic per-block partials (bce, mono, cnt, pad): each block fully
// overwrites its own slot every launch -> no init kernel needed.
__device__ float4 g_partials[MAXBLK];
// Completion counter: zero at load; last block resets to 0 -> replay-idempotent.
__device__ unsigned int g_count;

__device__ __forceinline__ float warp_red(float v) {
#pragma unroll
    for (int o = 16; o > 0; o >>= 1) v += __shfl_down_sync(0xFFFFFFFFu, v, o);
    return v;
}

__global__ __launch_bounds__(BDIM, 5) void cdf_loss_fused(
    const float* __restrict__ F,
    const long long* __restrict__ duration,
    const long long* __restrict__ event_in,
    const float* __restrict__ biases,
    float* __restrict__ out, int B)
{
    const int tid  = threadIdx.x;
    const int lane = tid & 31;
    const int wid  = tid >> 5;
    const int row0 = blockIdx.x * ROWS;
    const int c0   = tid * 4;
    const int nblk = gridDim.x;

    __shared__ float s_first[ROWS][BDIM];

    // per-row metadata packed: d | (e << 16)
    int meta[ROWS];
#pragma unroll
    for (int r = 0; r < ROWS; ++r) {
        const int dd = (int)duration[row0 + r];
        const int ee = (int)event_in[row0 + r];
        meta[r] = dd | (ee << 16);
    }

    // ---- front-batched independent bulk loads (MLP = ROWS) ----
    float4 v[ROWS];
#pragma unroll
    for (int r = 0; r < ROWS; ++r) {
        const float4* rowp = reinterpret_cast<const float4*>(F + (size_t)(row0 + r) * T_DIM);
        v[r] = rowp[tid];
    }

#pragma unroll
    for (int r = 0; r < ROWS; ++r)
        s_first[r][tid] = v[r].x;
    __syncthreads();   // single barrier: boundary values published

    float bce = 0.0f;
    float mono = 0.0f;
    int cnt = 0;

#pragma unroll
    for (int r = 0; r < ROWS; ++r) {
        const float4 w = v[r];

        // ---- monotonic term (verified mechanism) ----
        mono += fmaxf(w.x - w.y + MARGIN, 0.0f);
        mono += fmaxf(w.y - w.z + MARGIN, 0.0f);
        mono += fmaxf(w.z - w.w + MARGIN, 0.0f);
        if (tid < BDIM - 1)
            mono += fmaxf(w.w - s_first[r][tid + 1] + MARGIN, 0.0f);

        // ---- BCE term (verified math) ----
        const float vals[4] = {w.x, w.y, w.z, w.w};
        const int dd = meta[r] & 0xFFFF;
        const int ee = meta[r] >> 16;
#pragma unroll
        for (int k = 0; k < 4; ++k) {
            const int c = c0 + k;
            const bool m = ee ? true : (c <= dd);
            if (m) {
                cnt++;
                const float p = fminf(fmaxf(vals[k], EPS), 1.0f - EPS);
                const bool tgt = ee && (c >= dd);
                bce += -__logf(tgt ? p : (1.0f - p));
            }
        }
    }

    // ---- block reduction ----
    bce  = warp_red(bce);
    mono = warp_red(mono);
    float cf = warp_red((float)cnt);

    __shared__ float sh_b[BDIM / 32];
    __shared__ float sh_m[BDIM / 32];
    __shared__ float sh_c[BDIM / 32];
    if (lane == 0) { sh_b[wid] = bce; sh_m[wid] = mono; sh_c[wid] = cf; }
    __syncthreads();
    __shared__ bool is_last;
    if (tid == 0) is_last = false;
    if (wid == 0) {
        bce  = (lane < BDIM / 32) ? sh_b[lane] : 0.0f;
        mono = (lane < BDIM / 32) ? sh_m[lane] : 0.0f;
        cf   = (lane < BDIM / 32) ? sh_c[lane] : 0.0f;
        bce = warp_red(bce);
        mono = warp_red(mono);
        cf  = warp_red(cf);
        if (lane == 0) {
            g_partials[blockIdx.x] = make_float4(bce, mono, cf, 0.0f);
            __threadfence();   // publish partial before signaling
            unsigned int old = atomicInc(&g_count, 0xFFFFFFFFu);
            is_last = (old == (unsigned int)(nblk - 1));
        }
    }
    __syncthreads();
    if (!is_last) return;

    // ============ last block: fp32-only finalize (no fp64 register bloat) ====
    // Each thread sums nblk/BDIM (=16) partials into 4 independent fp32 sets.
    float fb0 = 0, fm0 = 0, fc0 = 0, fb1 = 0, fm1 = 0, fc1 = 0;
    float fb2 = 0, fm2 = 0, fc2 = 0, fb3 = 0, fm3 = 0, fc3 = 0;
    for (int i = tid; i < nblk; i += 4 * BDIM) {
        const float4 p0 = g_partials[i];
        fb0 += p0.x; fm0 += p0.y; fc0 += p0.z;
        if (i + BDIM < nblk) {
            const float4 p1 = g_partials[i + BDIM];
            fb1 += p1.x; fm1 += p1.y; fc1 += p1.z;
        }
        if (i + 2 * BDIM < nblk) {
            const float4 p2 = g_partials[i + 2 * BDIM];
            fb2 += p2.x; fm2 += p2.y; fc2 += p2.z;
        }
        if (i + 3 * BDIM < nblk) {
            const float4 p3 = g_partials[i + 3 * BDIM];
            fb3 += p3.x; fm3 += p3.y; fc3 += p3.z;
        }
    }
    float fb = (fb0 + fb1) + (fb2 + fb3);
    float fm = (fm0 + fm1) + (fm2 + fm3);
    float fc = (fc0 + fc1) + (fc2 + fc3);

    float s = 0.0f;
    for (int i = tid; i < T_DIM; i += BDIM) {
        const float b = biases[i];
        s += b * b;
    }

    fb = warp_red(fb);
    fm = warp_red(fm);
    fc = warp_red(fc);
    s  = warp_red(s);

    if (lane == 0) { sh_b[wid] = fb; sh_m[wid] = fm; sh_c[wid] = fc; }
    __shared__ float sh_s[BDIM / 32];
    if (lane == 0) sh_s[wid] = s;
    __syncthreads();
    if (wid == 0) {
        fb = (lane < BDIM / 32) ? sh_b[lane] : 0.0f;
        fm = (lane < BDIM / 32) ? sh_m[lane] : 0.0f;
        fc = (lane < BDIM / 32) ? sh_c[lane] : 0.0f;
        s  = (lane < BDIM / 32) ? sh_s[lane] : 0.0f;
        fb = warp_red(fb);
        fm = warp_red(fm);
        fc = warp_red(fc);
        s  = warp_red(s);
        if (lane == 0) {
            const float bceL  = fb / fc;
            const float monoL = fm / ((float)B * (float)(T_DIM - 1));
            const float bias2 = s / (float)T_DIM;
            out[0] = bceL + MONO_W * monoL + BETA * bias2;
            g_count = 0;   // reset for next replay
        }
    }
}

extern "C" void kernel_launch(void* const* d_in, const int* in_sizes, int n_in,
                              void* d_out, int out_size) {
    const float*     F      = (const float*)d_in[0];      // [B, T] fp32
    const float*     biases = (const float*)d_in[1];      // [T] fp32
    const long long* dur    = (const long long*)d_in[2];  // [B] int64
    const long long* ev     = (const long long*)d_in[3];  // [B] int64
    float* out = (float*)d_out;

    const int B = in_sizes[2];
    const int nblocks = B / ROWS;

    cdf_loss_fused<<<nblocks, BDIM>>>(F, dur, ev, biases, out, B);
}

// round 11
// speedup vs baseline: 1.6185x; 1.6185x over previous
#include <cuda_runtime.h>
#include <math.h>

#define T_DIM 1024
#define EPS 1e-7f
#define MARGIN 0.1f
#define MONO_W 0.1f
#define BETA 0.1f

#define BDIM 256            // 256 threads * float4 = 1024 cols = one row
#define ROWS 8              // rows per block
#define MAXB 32768
#define MAXBLK (MAXB / ROWS)

#define FDIM 1024           // finalize block size

// Deterministic per-block partials (bce, mono, cnt, pad): each block fully
// overwrites its own slot every launch -> no init kernel, no atomics.
__device__ float4 g_partials[MAXBLK];

__device__ __forceinline__ float warp_red(float v) {
#pragma unroll
    for (int o = 16; o > 0; o >>= 1) v += __shfl_down_sync(0xFFFFFFFFu, v, o);
    return v;
}
__device__ __forceinline__ double warp_red_d(double v) {
#pragma unroll
    for (int o = 16; o > 0; o >>= 1) v += __shfl_down_sync(0xFFFFFFFFu, v, o);
    return v;
}

__global__ __launch_bounds__(BDIM) void cdf_loss_main(
    const float* __restrict__ F,
    const long long* __restrict__ duration,
    const long long* __restrict__ event_in)
{
    const int tid  = threadIdx.x;
    const int lane = tid & 31;
    const int wid  = tid >> 5;
    const int row0 = blockIdx.x * ROWS;
    const int c0   = tid * 4;

    __shared__ float s_first[ROWS][BDIM];

    // per-row metadata packed into one register each: d | (e << 16)
    int meta[ROWS];
#pragma unroll
    for (int r = 0; r < ROWS; ++r) {
        const int dd = (int)duration[row0 + r];
        const int ee = (int)event_in[row0 + r];
        meta[r] = dd | (ee << 16);
    }

    // ---- front-batched independent bulk loads (MLP = ROWS) ----
    float4 v[ROWS];
#pragma unroll
    for (int r = 0; r < ROWS; ++r) {
        const float4* rowp = reinterpret_cast<const float4*>(F + (size_t)(row0 + r) * T_DIM);
        v[r] = rowp[tid];
    }

#pragma unroll
    for (int r = 0; r < ROWS; ++r)
        s_first[r][tid] = v[r].x;
    __syncthreads();   // single barrier: all rows' boundary values published

    float bce = 0.0f;
    float mono = 0.0f;
    int cnt = 0;

#pragma unroll
    for (int r = 0; r < ROWS; ++r) {
        const float4 w = v[r];

        // ---- monotonic term (verified mechanism) ----
        mono += fmaxf(w.x - w.y + MARGIN, 0.0f);
        mono += fmaxf(w.y - w.z + MARGIN, 0.0f);
        mono += fmaxf(w.z - w.w + MARGIN, 0.0f);
        if (tid < BDIM - 1)
            mono += fmaxf(w.w - s_first[r][tid + 1] + MARGIN, 0.0f);

        // ---- BCE term: log-of-product (1 MUFU.LG2 per 4 elements) ----
        // sum_{masked} -log(x_k) == -log( prod_{masked} x_k ); unmasked -> 1.0
        // x_k in [1e-7, 1] => prod >= 1e-28 > FLT_MIN (no underflow)
        const float vals[4] = {w.x, w.y, w.z, w.w};
        const int dd = meta[r] & 0xFFFF;
        const int ee = meta[r] >> 16;
        float prod = 1.0f;
#pragma unroll
        for (int k = 0; k < 4; ++k) {
            const int c = c0 + k;
            const bool m = ee ? true : (c <= dd);
            cnt += m;
            const float p = fminf(fmaxf(vals[k], EPS), 1.0f - EPS);
            const bool tgt = ee && (c >= dd);
            const float x = tgt ? p : (1.0f - p);
            prod *= m ? x : 1.0f;
        }
        bce += -__logf(prod);
    }

    // ---- block reduction ----
    bce  = warp_red(bce);
    mono = warp_red(mono);
    float cf = warp_red((float)cnt);

    __shared__ float sh_b[BDIM / 32];
    __shared__ float sh_m[BDIM / 32];
    __shared__ float sh_c[BDIM / 32];
    if (lane == 0) { sh_b[wid] = bce; sh_m[wid] = mono; sh_c[wid] = cf; }
    __syncthreads();
    if (wid == 0) {
        bce  = (lane < BDIM / 32) ? sh_b[lane] : 0.0f;
        mono = (lane < BDIM / 32) ? sh_m[lane] : 0.0f;
        cf   = (lane < BDIM / 32) ? sh_c[lane] : 0.0f;
        bce = warp_red(bce);
        mono = warp_red(mono);
        cf  = warp_red(cf);
        if (lane == 0)
            g_partials[blockIdx.x] = make_float4(bce, mono, cf, 0.0f);
    }
}

__global__ __launch_bounds__(FDIM) void cdf_loss_finalize(
    const float* __restrict__ biases,
    float* __restrict__ out, int B)
{
    const int tid = threadIdx.x;
    const int lane = tid & 31, wid = tid >> 5;
    const int nblk = B / ROWS;   // 4096 for B=32768

    // 4 independent accumulator sets; each thread loads exactly nblk/FDIM (=4)
    // partials, all loads issued before any dependent DADD chains bind.
    double sb0 = 0, sm0 = 0, sc0 = 0, sb1 = 0, sm1 = 0, sc1 = 0;
    double sb2 = 0, sm2 = 0, sc2 = 0, sb3 = 0, sm3 = 0, sc3 = 0;
    {
        float4 p0 = make_float4(0, 0, 0, 0), p1 = p0, p2 = p0, p3 = p0;
        const int i0 = tid, i1 = tid + FDIM, i2 = tid + 2 * FDIM, i3 = tid + 3 * FDIM;
        if (i0 < nblk) p0 = g_partials[i0];
        if (i1 < nblk) p1 = g_partials[i1];
        if (i2 < nblk) p2 = g_partials[i2];
        if (i3 < nblk) p3 = g_partials[i3];
        sb0 += p0.x; sm0 += p0.y; sc0 += p0.z;
        sb1 += p1.x; sm1 += p1.y; sc1 += p1.z;
        sb2 += p2.x; sm2 += p2.y; sc2 += p2.z;
        sb3 += p3.x; sm3 += p3.y; sc3 += p3.z;
        for (int i = tid + 4 * FDIM; i < nblk; i += FDIM) {
            const float4 p = g_partials[i];
            sb0 += p.x; sm0 += p.y; sc0 += p.z;
        }
    }
    double sb = (sb0 + sb1) + (sb2 + sb3);
    double sm = (sm0 + sm1) + (sm2 + sm3);
    double sc = (sc0 + sc1) + (sc2 + sc3);

    float s = (tid < T_DIM) ? biases[tid] : 0.0f;
    s = s * s;

    sb = warp_red_d(sb);
    sm = warp_red_d(sm);
    sc = warp_red_d(sc);
    s  = warp_red(s);

    __shared__ double shb[FDIM / 32], shm[FDIM / 32], shc[FDIM / 32];
    __shared__ float  shs[FDIM / 32];
    if (lane == 0) { shb[wid] = sb; shm[wid] = sm; shc[wid] = sc; shs[wid] = s; }
    __syncthreads();
    if (wid == 0) {
        sb = (lane < FDIM / 32) ? shb[lane] : 0.0;
        sm = (lane < FDIM / 32) ? shm[lane] : 0.0;
        sc = (lane < FDIM / 32) ? shc[lane] : 0.0;
        s  = (lane < FDIM / 32) ? shs[lane] : 0.0f;
        sb = warp_red_d(sb);
        sm = warp_red_d(sm);
        sc = warp_red_d(sc);
        s  = warp_red(s);
        if (lane == 0) {
            const double bceL  = sb / sc;
            const double monoL = sm / ((double)B * (double)(T_DIM - 1));
            const double bias2 = (double)s / (double)T_DIM;
            out[0] = (float)(bceL + (double)MONO_W * monoL + (double)BETA * bias2);
        }
    }
}

extern "C" void kernel_launch(void* const* d_in, const int* in_sizes, int n_in,
                              void* d_out, int out_size) {
    const float*     F      = (const float*)d_in[0];      // [B, T] fp32
    const float*     biases = (const float*)d_in[1];      // [T] fp32
    const long long* dur    = (const long long*)d_in[2];  // [B] int64
    const long long* ev     = (const long long*)d_in[3];  // [B] int64
    float* out = (float*)d_out;

    const int B = in_sizes[2];
    const int nblocks = B / ROWS;

    cdf_loss_main<<<nblocks, BDIM>>>(F, dur, ev);
    cdf_loss_finalize<<<1, FDIM>>>(biases, out, B);
}

// round 12
// speedup vs baseline: 1.7263x; 1.0666x over previous
#include <cuda_runtime.h>
#include <math.h>

#define T_DIM 1024
#define EPS 1e-7f
#define MARGIN 0.1f
#define MONO_W 0.1f
#define BETA 0.1f

#define BDIM 256            // 256 threads * float4 = 1024 cols = one row
#define ROWS 8              // rows per block
#define MAXB 32768
#define MAXBLK (MAXB / ROWS)

#define FDIM 1024           // finalize block size

// Deterministic per-block partials (bce, mono, cnt, pad): each block fully
// overwrites its own slot every launch -> no init kernel, no atomics.
__device__ float4 g_partials[MAXBLK];

__device__ __forceinline__ float warp_red(float v) {
#pragma unroll
    for (int o = 16; o > 0; o >>= 1) v += __shfl_down_sync(0xFFFFFFFFu, v, o);
    return v;
}
__device__ __forceinline__ double warp_red_d(double v) {
#pragma unroll
    for (int o = 16; o > 0; o >>= 1) v += __shfl_down_sync(0xFFFFFFFFu, v, o);
    return v;
}

__global__ __launch_bounds__(BDIM) void cdf_loss_main(
    const float* __restrict__ F,
    const long long* __restrict__ duration,
    const long long* __restrict__ event_in)
{
    const int tid  = threadIdx.x;
    const int lane = tid & 31;
    const int wid  = tid >> 5;
    const int row0 = blockIdx.x * ROWS;
    const int c0   = tid * 4;

    __shared__ float s_first[ROWS][BDIM];

    // per-row metadata packed: d | (e << 16); analytic block mask count
    int meta[ROWS];
    int cnt_blk = 0;
#pragma unroll
    for (int r = 0; r < ROWS; ++r) {
        const int dd = (int)duration[row0 + r];
        const int ee = (int)event_in[row0 + r];
        meta[r] = dd | (ee << 16);
        cnt_blk += ee ? T_DIM : (dd + 1);
    }

    // ---- front-batched independent bulk loads (MLP = ROWS) ----
    float4 v[ROWS];
#pragma unroll
    for (int r = 0; r < ROWS; ++r) {
        const float4* rowp = reinterpret_cast<const float4*>(F + (size_t)(row0 + r) * T_DIM);
        v[r] = rowp[tid];
    }

#pragma unroll
    for (int r = 0; r < ROWS; ++r)
        s_first[r][tid] = v[r].x;
    __syncthreads();   // single barrier: all rows' boundary values published

    float bce = 0.0f;
    float mono = 0.0f;

#pragma unroll
    for (int r = 0; r < ROWS; ++r) {
        const float4 w = v[r];

        // ---- monotonic term (verified mechanism) ----
        mono += fmaxf(w.x - w.y + MARGIN, 0.0f);
        mono += fmaxf(w.y - w.z + MARGIN, 0.0f);
        mono += fmaxf(w.z - w.w + MARGIN, 0.0f);
        if (tid < BDIM - 1)
            mono += fmaxf(w.w - s_first[r][tid + 1] + MARGIN, 0.0f);

        // ---- BCE term: warp-uniform case split, 1 MUFU.LG2 per group ----
        const int dd = meta[r] & 0xFFFF;
        const int ee = meta[r] >> 16;
        // all four columns take the (1-p) factor when c0+3 <= dd - ee
        //   (ee=1 needs c < dd; ee=0 needs c <= dd)
        const int thr = dd - ee;
        float prod;
        if (c0 + 3 <= thr) {
            // uniform: all masked, target=0 -> factor (1-p); no clamp needed
            prod = (1.0f - w.x) * (1.0f - w.y) * (1.0f - w.z) * (1.0f - w.w);
        } else if (ee && c0 >= dd) {
            // uniform: all masked, target=1 -> factor max(p, EPS)
            prod = fmaxf(w.x, EPS) * fmaxf(w.y, EPS) *
                   fmaxf(w.z, EPS) * fmaxf(w.w, EPS);
        } else if (c0 <= dd) {
            // mixed boundary group (~1 thread per row): generic per-element
            const float vals[4] = {w.x, w.y, w.z, w.w};
            prod = 1.0f;
#pragma unroll
            for (int k = 0; k < 4; ++k) {
                const int c = c0 + k;
                const bool use_p = ee && (c >= dd);
                const bool msk   = ee || (c <= dd);
                const float x = use_p ? fmaxf(vals[k], EPS) : (1.0f - vals[k]);
                prod *= msk ? x : 1.0f;
            }
        } else {
            // ee=0 and c0 > dd: fully unmasked -> no contribution
            prod = 1.0f;
        }
        bce += -__logf(prod);   // __logf(1)=0 exactly
    }

    // ---- block reduction (bce, mono only; cnt is analytic) ----
    bce  = warp_red(bce);
    mono = warp_red(mono);

    __shared__ float sh_b[BDIM / 32];
    __shared__ float sh_m[BDIM / 32];
    if (lane == 0) { sh_b[wid] = bce; sh_m[wid] = mono; }
    __syncthreads();
    if (wid == 0) {
        bce  = (lane < BDIM / 32) ? sh_b[lane] : 0.0f;
        mono = (lane < BDIM / 32) ? sh_m[lane] : 0.0f;
        bce = warp_red(bce);
        mono = warp_red(mono);
        if (lane == 0)
            g_partials[blockIdx.x] = make_float4(bce, mono, (float)cnt_blk, 0.0f);
    }
}

__global__ __launch_bounds__(FDIM) void cdf_loss_finalize(
    const float* __restrict__ biases,
    float* __restrict__ out, int B)
{
    const int tid = threadIdx.x;
    const int lane = tid & 31, wid = tid >> 5;
    const int nblk = B / ROWS;   // 4096 for B=32768

    double sb0 = 0, sm0 = 0, sc0 = 0, sb1 = 0, sm1 = 0, sc1 = 0;
    double sb2 = 0, sm2 = 0, sc2 = 0, sb3 = 0, sm3 = 0, sc3 = 0;
    {
        float4 p0 = make_float4(0, 0, 0, 0), p1 = p0, p2 = p0, p3 = p0;
        const int i0 = tid, i1 = tid + FDIM, i2 = tid + 2 * FDIM, i3 = tid + 3 * FDIM;
        if (i0 < nblk) p0 = g_partials[i0];
        if (i1 < nblk) p1 = g_partials[i1];
        if (i2 < nblk) p2 = g_partials[i2];
        if (i3 < nblk) p3 = g_partials[i3];
        sb0 += p0.x; sm0 += p0.y; sc0 += p0.z;
        sb1 += p1.x; sm1 += p1.y; sc1 += p1.z;
        sb2 += p2.x; sm2 += p2.y; sc2 += p2.z;
        sb3 += p3.x; sm3 += p3.y; sc3 += p3.z;
        for (int i = tid + 4 * FDIM; i < nblk; i += FDIM) {
            const float4 p = g_partials[i];
            sb0 += p.x; sm0 += p.y; sc0 += p.z;
        }
    }
    double sb = (sb0 + sb1) + (sb2 + sb3);
    double sm = (sm0 + sm1) + (sm2 + sm3);
    double sc = (sc0 + sc1) + (sc2 + sc3);

    float s = (tid < T_DIM) ? biases[tid] : 0.0f;
    s = s * s;

    sb = warp_red_d(sb);
    sm = warp_red_d(sm);
    sc = warp_red_d(sc);
    s  = warp_red(s);

    __shared__ double shb[FDIM / 32], shm[FDIM / 32], shc[FDIM / 32];
    __shared__ float  shs[FDIM / 32];
    if (lane == 0) { shb[wid] = sb; shm[wid] = sm; shc[wid] = sc; shs[wid] = s; }
    __syncthreads();
    if (wid == 0) {
        sb = (lane < FDIM / 32) ? shb[lane] : 0.0;
        sm = (lane < FDIM / 32) ? shm[lane] : 0.0;
        sc = (lane < FDIM / 32) ? shc[lane] : 0.0;
        s  = (lane < FDIM / 32) ? shs[lane] : 0.0f;
        sb = warp_red_d(sb);
        sm = warp_red_d(sm);
        sc = warp_red_d(sc);
        s  = warp_red(s);
        if (lane == 0) {
            const double bceL  = sb / sc;
            const double monoL = sm / ((double)B * (double)(T_DIM - 1));
            const double bias2 = (double)s / (double)T_DIM;
            out[0] = (float)(bceL + (double)MONO_W * monoL + (double)BETA * bias2);
        }
    }
}

extern "C" void kernel_launch(void* const* d_in, const int* in_sizes, int n_in,
                              void* d_out, int out_size) {
    const float*     F      = (const float*)d_in[0];      // [B, T] fp32
    const float*     biases = (const float*)d_in[1];      // [T] fp32
    const long long* dur    = (const long long*)d_in[2];  // [B] int64
    const long long* ev     = (const long long*)d_in[3];  // [B] int64
    float* out = (float*)d_out;

    const int B = in_sizes[2];
    const int nblocks = B / ROWS;

    cdf_loss_main<<<nblocks, BDIM>>>(F, dur, ev);
    cdf_loss_finalize<<<1, FDIM>>>(biases, out, B);
}